// round 14
// baseline (speedup 1.0000x reference)
#include <cuda_runtime.h>
#include <cuda_bf16.h>
#include <math.h>
#include <stdint.h>

#define Nn 10000
#define Ee 160000
#define HID 256
#define HEADS 8
#define Cc 32
#define Tt 5
#define EDGE_DIM 9
#define GNODE 4   // nodes per attention block

// ---------------- scratch (static device globals; no allocation) ----------------
__device__ float g_ea[Ee * EDGE_DIM];
__device__ float g_h[Nn * HID];
__device__ float g_xl[Nn * HID];
__device__ float g_xr[Nn * HID];
__device__ float g_out[Nn * HID];
__device__ int   g_cnt[Nn + 1];
__device__ int   g_off[Nn + 1];
__device__ int   g_cur[Nn];
__device__ int   g_elist[Ee];
__device__ double g_red[8 * 512];   // slots: 0-4 GAT layers, 5-6 proj, 7 ea
__device__ float g_eap[2 * EDGE_DIM];
// bf16 hi/lo copies for tensor-core GEMM
__device__ __nv_bfloat16 g_hh[Nn * HID];
__device__ __nv_bfloat16 g_hl[Nn * HID];
__device__ __nv_bfloat16 g_Wbh[12 * HID * HID];
__device__ __nv_bfloat16 g_Wbl[12 * HID * HID];

// ---------------- utility ----------------
__global__ void zero_red_k() { int i = blockIdx.x * 256 + threadIdx.x; if (i < 8 * 512) g_red[i] = 0.0; }
__global__ void zero_cnt_k() { int i = blockIdx.x * 256 + threadIdx.x; if (i <= Nn) g_cnt[i] = 0; }

__device__ __forceinline__ void split1(float x, __nv_bfloat16& hi, __nv_bfloat16& lo) {
    hi = __float2bfloat16_rn(x);
    lo = __float2bfloat16_rn(x - __bfloat162float(hi));
}

// ---------------- weight pre-conversion: 12 slots of 256x256 ----------------
__global__ void wconv_k(const float* __restrict__ Wl, const float* __restrict__ Wr,
                        const float* __restrict__ p1, const float* __restrict__ p2) {
    int idx = blockIdx.x * 256 + threadIdx.x;
    int slot = idx >> 16, e = idx & 65535;
    float v;
    if (slot < 5)       v = Wl[slot * 65536 + e];
    else if (slot < 10) v = Wr[(slot - 5) * 65536 + e];
    else if (slot == 10) v = p1[e];
    else                 v = p2[e];
    __nv_bfloat16 hi, lo;
    split1(v, hi, lo);
    g_Wbh[idx] = hi; g_Wbl[idx] = lo;
}

// ---------------- edge-attr normalization (slot 7) ----------------
__global__ void ea_stats_k(const float* __restrict__ ea) {
    __shared__ double ss[EDGE_DIM], ss2[EDGE_DIM];
    if (threadIdx.x < EDGE_DIM) { ss[threadIdx.x] = 0.0; ss2[threadIdx.x] = 0.0; }
    __syncthreads();
    double ls[EDGE_DIM] = {0}, ls2[EDGE_DIM] = {0};
    for (int e = blockIdx.x * blockDim.x + threadIdx.x; e < Ee; e += gridDim.x * blockDim.x) {
        #pragma unroll
        for (int k = 0; k < EDGE_DIM; k++) {
            float x = ea[e * EDGE_DIM + k];
            ls[k] += x; ls2[k] += (double)x * x;
        }
    }
    #pragma unroll
    for (int k = 0; k < EDGE_DIM; k++) { atomicAdd(&ss[k], ls[k]); atomicAdd(&ss2[k], ls2[k]); }
    __syncthreads();
    if (threadIdx.x < EDGE_DIM) {
        atomicAdd(&g_red[7 * 512 + threadIdx.x], ss[threadIdx.x]);
        atomicAdd(&g_red[7 * 512 + 256 + threadIdx.x], ss2[threadIdx.x]);
    }
}

__global__ void ea_final_k() {
    int c = threadIdx.x;
    if (c < EDGE_DIM) {
        double mu = g_red[7 * 512 + c] / (double)Ee;
        double var = g_red[7 * 512 + 256 + c] / (double)Ee - mu * mu;
        double sd = sqrt(var > 0.0 ? var : 0.0);
        g_eap[c] = (float)mu;
        g_eap[EDGE_DIM + c] = (float)(1.0 / (sd + 1e-8));
    }
}

__global__ void ea_norm_k(const float* __restrict__ ea) {
    int idx = blockIdx.x * 256 + threadIdx.x;
    if (idx < Ee * EDGE_DIM) {
        int c = idx % EDGE_DIM;
        g_ea[idx] = (ea[idx] - g_eap[c]) * g_eap[EDGE_DIM + c];
    }
}

// ---------------- lift ----------------
__global__ void lift_k(const float* __restrict__ x, const float* __restrict__ W,
                       const float* __restrict__ b) {
    int n = blockIdx.x;
    int c = threadIdx.x;
    float acc = b[c];
    #pragma unroll
    for (int k = 0; k < 10; k++) acc += x[n * 10 + k] * W[k * HID + c];
    float h = fmaxf(acc, 0.f);
    g_h[n * HID + c] = h;
    __nv_bfloat16 hi, lo;
    split1(h, hi, lo);
    g_hh[n * HID + c] = hi; g_hl[n * HID + c] = lo;
}

// ---------------- CSR build ----------------
__global__ void hist_k(const int* __restrict__ ei) {
    int e = blockIdx.x * 256 + threadIdx.x;
    if (e < Ee) atomicAdd(&g_cnt[ei[Ee + e]], 1);
}

__global__ void scan_k() {
    __shared__ int partial[1024];
    int tid = threadIdx.x;
    const int PER = 10;
    int base = tid * PER;
    int loc[PER];
    int s = 0;
    #pragma unroll
    for (int i = 0; i < PER; i++) {
        int n = base + i;
        int v = (n < Nn) ? g_cnt[n] : 0;
        loc[i] = s; s += v;
    }
    partial[tid] = s;
    __syncthreads();
    for (int off = 1; off < 1024; off <<= 1) {
        int v = (tid >= off) ? partial[tid - off] : 0;
        __syncthreads();
        partial[tid] += v;
        __syncthreads();
    }
    int offset = (tid > 0) ? partial[tid - 1] : 0;
    #pragma unroll
    for (int i = 0; i < PER; i++) {
        int n = base + i;
        if (n < Nn) { g_off[n] = offset + loc[i]; g_cur[n] = offset + loc[i]; }
    }
    if (tid == 1023) g_off[Nn] = partial[1023];
}

__global__ void fill_k(const int* __restrict__ ei) {
    int e = blockIdx.x * 256 + threadIdx.x;
    if (e < Ee) {
        int pos = atomicAdd(&g_cur[ei[Ee + e]], 1);
        g_elist[pos] = e;
    }
}

// ================= bf16-split HMMA GEMM, cp.async double-buffered =================
#define STG_STRIDE 37888
#define GSM_DYN    (2 * STG_STRIDE)

__device__ __forceinline__ uint32_t smem_u32(const void* p) {
    uint32_t a;
    asm("{ .reg .u64 t; cvta.to.shared.u64 t, %1; cvt.u32.u64 %0, t; }" : "=r"(a) : "l"(p));
    return a;
}
__device__ __forceinline__ void cp16(uint32_t dst, const void* src) {
    asm volatile("cp.async.cg.shared.global [%0], [%1], 16;" :: "r"(dst), "l"(src) : "memory");
}
__device__ __forceinline__ void ldsm_x4(uint32_t* r, uint32_t addr) {
    asm volatile("ldmatrix.sync.aligned.m8n8.x4.shared.b16 {%0,%1,%2,%3}, [%4];"
                 : "=r"(r[0]), "=r"(r[1]), "=r"(r[2]), "=r"(r[3]) : "r"(addr));
}
__device__ __forceinline__ void ldsm_x4_t(uint32_t* r, uint32_t addr) {
    asm volatile("ldmatrix.sync.aligned.m8n8.x4.trans.shared.b16 {%0,%1,%2,%3}, [%4];"
                 : "=r"(r[0]), "=r"(r[1]), "=r"(r[2]), "=r"(r[3]) : "r"(addr));
}
__device__ __forceinline__ void mma_bf16(float& d0, float& d1, float& d2, float& d3,
                                         const uint32_t* a, uint32_t b0, uint32_t b1) {
    asm volatile(
        "mma.sync.aligned.m16n8k16.row.col.f32.bf16.bf16.f32 "
        "{%0,%1,%2,%3}, {%4,%5,%6,%7}, {%8,%9}, {%0,%1,%2,%3};"
        : "+f"(d0), "+f"(d1), "+f"(d2), "+f"(d3)
        : "r"(a[0]), "r"(a[1]), "r"(a[2]), "r"(a[3]), "r"(b0), "r"(b1));
}

__global__ void __launch_bounds__(256, 2)
hgemm_k(const __nv_bfloat16* __restrict__ Bh0, const __nv_bfloat16* __restrict__ Bl0,
        const float* __restrict__ b0, float* __restrict__ Y0,
        const __nv_bfloat16* __restrict__ Bh1, const __nv_bfloat16* __restrict__ Bl1,
        const float* __restrict__ b1, float* __restrict__ Y1,
        int M) {
    extern __shared__ __align__(16) char sm[];
    const uint32_t sb = smem_u32(sm);
    const int tid = threadIdx.x;
    const int wid = tid >> 5, lane = tid & 31;
    const int bm = blockIdx.x * 128, bn = blockIdx.y * 128;
    const __nv_bfloat16* Bh  = blockIdx.z ? Bh1 : Bh0;
    const __nv_bfloat16* Bl  = blockIdx.z ? Bl1 : Bl0;
    const float* bias        = blockIdx.z ? b1 : b0;
    float*       Y           = blockIdx.z ? Y1 : Y0;

    const int warp_m = (wid >> 1) * 32;
    const int warp_n = (wid & 1) * 64;

    const int ar = tid >> 1, akseg = (tid & 1) * 16;
    const int arow_g = min(bm + ar, M - 1);
    const __nv_bfloat16* gAh = g_hh + (size_t)arow_g * 256 + akseg;
    const __nv_bfloat16* gAl = g_hl + (size_t)arow_g * 256 + akseg;
    const int br_ = tid >> 3, bcseg = (tid & 7) * 16;
    const __nv_bfloat16* gBh = Bh + (size_t)br_ * 256 + bn + bcseg;
    const __nv_bfloat16* gBl = Bl + (size_t)br_ * 256 + bn + bcseg;
    const uint32_t aoff = (uint32_t)(ar * 80 + akseg * 2);
    const uint32_t boff = (uint32_t)(br_ * 272 + bcseg * 2);

    float acc[2][8][4];
    #pragma unroll
    for (int i = 0; i < 2; i++)
        #pragma unroll
        for (int j = 0; j < 8; j++)
            #pragma unroll
            for (int k = 0; k < 4; k++) acc[i][j][k] = 0.f;

    const uint32_t aRelH = (uint32_t)((warp_m + (lane & 15)) * 80 + (lane >> 4) * 16);
    const int bg = lane >> 3;
    const uint32_t bRelH = 20480u + (uint32_t)(((bg & 1) * 8 + (lane & 7)) * 272
                         + (warp_n + (bg >> 1) * 8) * 2);

    auto fill = [&](int c, int s) {
        uint32_t base = sb + (uint32_t)s * STG_STRIDE;
        const __nv_bfloat16* pa = gAh + c * 32;
        const __nv_bfloat16* pl = gAl + c * 32;
        const __nv_bfloat16* ph = gBh + (size_t)(c * 32) * 256;
        const __nv_bfloat16* pb = gBl + (size_t)(c * 32) * 256;
        cp16(base + aoff, pa);                 cp16(base + aoff + 16, pa + 8);
        cp16(base + 10240 + aoff, pl);         cp16(base + 10240 + aoff + 16, pl + 8);
        cp16(base + 20480 + boff, ph);         cp16(base + 20480 + boff + 16, ph + 8);
        cp16(base + 29184 + boff, pb);         cp16(base + 29184 + boff + 16, pb + 8);
        asm volatile("cp.async.commit_group;" ::: "memory");
    };

    fill(0, 0);

    #pragma unroll 1
    for (int kc = 0; kc < 8; kc++) {
        const int s = kc & 1;
        if (kc < 7) {
            fill(kc + 1, s ^ 1);
            asm volatile("cp.async.wait_group 1;" ::: "memory");
        } else {
            asm volatile("cp.async.wait_group 0;" ::: "memory");
        }
        __syncthreads();

        const uint32_t stg = sb + (uint32_t)s * STG_STRIDE;
        #pragma unroll
        for (int ks = 0; ks < 2; ks++) {
            uint32_t bh[4][4], bl[4][4];
            #pragma unroll
            for (int nt = 0; nt < 4; nt++) {
                uint32_t off = (uint32_t)(ks * 16) * 272 + (uint32_t)(nt * 16) * 2;
                ldsm_x4_t(bh[nt], stg + bRelH + off);
                ldsm_x4_t(bl[nt], stg + bRelH + 8704 + off);
            }
            #pragma unroll
            for (int mt = 0; mt < 2; mt++) {
                uint32_t ah[4], al[4];
                uint32_t aoff2 = (uint32_t)(mt * 16) * 80 + (uint32_t)(ks * 32);
                ldsm_x4(ah, stg + aRelH + aoff2);
                ldsm_x4(al, stg + 10240 + aRelH + aoff2);
                #pragma unroll
                for (int nt = 0; nt < 4; nt++) {
                    float* d0 = acc[mt][nt * 2];
                    float* d1 = acc[mt][nt * 2 + 1];
                    mma_bf16(d0[0], d0[1], d0[2], d0[3], ah, bh[nt][0], bh[nt][1]);
                    mma_bf16(d1[0], d1[1], d1[2], d1[3], ah, bh[nt][2], bh[nt][3]);
                    mma_bf16(d0[0], d0[1], d0[2], d0[3], ah, bl[nt][0], bl[nt][1]);
                    mma_bf16(d1[0], d1[1], d1[2], d1[3], ah, bl[nt][2], bl[nt][3]);
                    mma_bf16(d0[0], d0[1], d0[2], d0[3], al, bh[nt][0], bh[nt][1]);
                    mma_bf16(d1[0], d1[1], d1[2], d1[3], al, bh[nt][2], bh[nt][3]);
                }
            }
        }
        __syncthreads();
    }

    const int crow = lane >> 2, ccol = (lane & 3) * 2;
    #pragma unroll
    for (int mt = 0; mt < 2; mt++) {
        int row0 = bm + warp_m + mt * 16 + crow;
        #pragma unroll
        for (int nt8 = 0; nt8 < 8; nt8++) {
            int col = bn + warp_n + nt8 * 8 + ccol;
            float bx = bias[col], by = bias[col + 1];
            if (row0 < M) {
                float2 o = make_float2(acc[mt][nt8][0] + bx, acc[mt][nt8][1] + by);
                *reinterpret_cast<float2*>(Y + (size_t)row0 * 256 + col) = o;
            }
            if (row0 + 8 < M) {
                float2 o = make_float2(acc[mt][nt8][2] + bx, acc[mt][nt8][3] + by);
                *reinterpret_cast<float2*>(Y + (size_t)(row0 + 8) * 256 + col) = o;
            }
        }
    }
}

// ================= single-pass fused GATv2 attention (flash-style) + BN stats =================
// Block handles GNODE nodes; 128 threads (4 warps). Each warp streams a subset of the
// node's edges: computes the logit (xl row held in registers), quad-shuffles to get the
// full head logit in every lane, then does the online-softmax update in registers.
// Cross-warp merge per node in smem (warp 0), which also writes output + BN sums.
__global__ void __launch_bounds__(128)
attn_fused_k(const int* __restrict__ ei, const float* __restrict__ We_,
             const float* __restrict__ att, const float* __restrict__ bias, int slot) {
    __shared__ float s_xr[256];
    __shared__ float s_m[4][32];
    __shared__ float s_den[4][32];
    __shared__ float s_acc[4][256];

    const int tid = threadIdx.x, wid = tid >> 5, lane = tid & 31;

    // register We (lane owns channels lane*8..lane*8+7, all within head lane>>2) and att
    float rWe[9][8], rAtt[8], rB[8];
    {
        const float4* w4 = reinterpret_cast<const float4*>(We_);
        #pragma unroll
        for (int k = 0; k < 9; k++) {
            float4 a = w4[k * 64 + lane * 2];
            float4 b = w4[k * 64 + lane * 2 + 1];
            rWe[k][0] = a.x; rWe[k][1] = a.y; rWe[k][2] = a.z; rWe[k][3] = a.w;
            rWe[k][4] = b.x; rWe[k][5] = b.y; rWe[k][6] = b.z; rWe[k][7] = b.w;
        }
        const float4* a4 = reinterpret_cast<const float4*>(att);
        float4 a = a4[lane * 2], b = a4[lane * 2 + 1];
        rAtt[0] = a.x; rAtt[1] = a.y; rAtt[2] = a.z; rAtt[3] = a.w;
        rAtt[4] = b.x; rAtt[5] = b.y; rAtt[6] = b.z; rAtt[7] = b.w;
        const float4* b4 = reinterpret_cast<const float4*>(bias);
        float4 c = b4[lane * 2], d = b4[lane * 2 + 1];
        rB[0] = c.x; rB[1] = c.y; rB[2] = c.z; rB[3] = c.w;
        rB[4] = d.x; rB[5] = d.y; rB[6] = d.z; rB[7] = d.w;
    }

    double bsum[8] = {0,0,0,0,0,0,0,0}, bsq[8] = {0,0,0,0,0,0,0,0};  // warp 0 only

    #pragma unroll 1
    for (int g = 0; g < GNODE; g++) {
        const int n = blockIdx.x * GNODE + g;
        const int start = g_off[n], deg = g_off[n + 1] - start;

        __syncthreads();   // previous node fully consumed before s_xr overwrite
        s_xr[tid] = g_xr[n * 256 + tid];
        s_xr[tid + 128] = g_xr[n * 256 + tid + 128];
        __syncthreads();

        float m = -1e30f, den = 0.f;
        float acc[8];
        #pragma unroll
        for (int c = 0; c < 8; c++) acc[c] = 0.f;

        const float4* r4 = reinterpret_cast<const float4*>(s_xr);
        float4 r0 = r4[lane * 2], r1 = r4[lane * 2 + 1];

        for (int i = wid; i < deg; i += 4) {
            int e = g_elist[start + i];
            int src = __ldg(ei + e);
            float a9 = (lane < EDGE_DIM) ? g_ea[e * EDGE_DIM + lane] : 0.f;
            const float4* xl4 = reinterpret_cast<const float4*>(g_xl + (size_t)src * 256);
            float4 x0 = xl4[lane * 2], x1 = xl4[lane * 2 + 1];
            float xc[8] = {x0.x, x0.y, x0.z, x0.w, x1.x, x1.y, x1.z, x1.w};
            float v[8];
            v[0] = xc[0] + r0.x; v[1] = xc[1] + r0.y; v[2] = xc[2] + r0.z; v[3] = xc[3] + r0.w;
            v[4] = xc[4] + r1.x; v[5] = xc[5] + r1.y; v[6] = xc[6] + r1.z; v[7] = xc[7] + r1.w;
            #pragma unroll
            for (int k = 0; k < EDGE_DIM; k++) {
                float eak = __shfl_sync(0xffffffffu, a9, k);
                #pragma unroll
                for (int c = 0; c < 8; c++) v[c] = fmaf(eak, rWe[k][c], v[c]);
            }
            float p = 0.f;
            #pragma unroll
            for (int c = 0; c < 8; c++) {
                float t = v[c] > 0.f ? v[c] : 0.2f * v[c];
                p = fmaf(t, rAtt[c], p);
            }
            p += __shfl_xor_sync(0xffffffffu, p, 1);
            p += __shfl_xor_sync(0xffffffffu, p, 2);   // full head logit in every lane

            // online softmax update (per-lane state, head = lane>>2)
            float mn = fmaxf(m, p);
            float sc = expf(m - mn);
            float w  = expf(p - mn);
            den = den * sc + w;
            #pragma unroll
            for (int c = 0; c < 8; c++) acc[c] = fmaf(acc[c], sc, w * xc[c]);
            m = mn;
        }

        // publish warp partials
        s_m[wid][lane] = m;
        s_den[wid][lane] = den;
        *reinterpret_cast<float4*>(&s_acc[wid][lane * 8])     = make_float4(acc[0], acc[1], acc[2], acc[3]);
        *reinterpret_cast<float4*>(&s_acc[wid][lane * 8 + 4]) = make_float4(acc[4], acc[5], acc[6], acc[7]);
        __syncthreads();

        if (wid == 0) {
            float M = -1e30f;
            #pragma unroll
            for (int w = 0; w < 4; w++) M = fmaxf(M, s_m[w][lane]);
            float D = 0.f, o[8];
            #pragma unroll
            for (int c = 0; c < 8; c++) o[c] = 0.f;
            #pragma unroll
            for (int w = 0; w < 4; w++) {
                float sc = expf(s_m[w][lane] - M);
                D = fmaf(s_den[w][lane], sc, D);
                #pragma unroll
                for (int c = 0; c < 8; c++) o[c] = fmaf(s_acc[w][lane * 8 + c], sc, o[c]);
            }
            float inv = (deg == 0) ? 0.f : 1.f / (D + 1e-16f);
            float ov[8];
            #pragma unroll
            for (int c = 0; c < 8; c++) {
                ov[c] = o[c] * inv + rB[c];
                bsum[c] += ov[c]; bsq[c] += (double)ov[c] * ov[c];
            }
            float* op = g_out + (size_t)n * 256 + lane * 8;
            *reinterpret_cast<float4*>(op)     = make_float4(ov[0], ov[1], ov[2], ov[3]);
            *reinterpret_cast<float4*>(op + 4) = make_float4(ov[4], ov[5], ov[6], ov[7]);
        }
    }

    if (wid == 0) {
        #pragma unroll
        for (int c = 0; c < 8; c++) {
            atomicAdd(&g_red[slot * 512 + lane * 8 + c], bsum[c]);
            atomicAdd(&g_red[slot * 512 + 256 + lane * 8 + c], bsq[c]);
        }
    }
}

// ---------------- BatchNorm (slot-based) ----------------
__global__ void bn_stats_k(const float* __restrict__ v, int slot) {
    int c = threadIdx.x;
    double s = 0.0, s2 = 0.0;
    for (int n = blockIdx.x; n < Nn; n += gridDim.x) {
        float x = v[n * HID + c];
        s += x; s2 += (double)x * x;
    }
    atomicAdd(&g_red[slot * 512 + c], s);
    atomicAdd(&g_red[slot * 512 + 256 + c], s2);
}

// act: 0 = elu, 1 = relu; computes scale/shift from slot; emits bf16 hi/lo
__global__ void bn_apply_k(const float* __restrict__ v, float* __restrict__ o, int act,
                           int slot, const float* __restrict__ gamma,
                           const float* __restrict__ beta) {
    int c = threadIdx.x;
    double mu = g_red[slot * 512 + c] * (1.0 / Nn);
    double var = g_red[slot * 512 + 256 + c] * (1.0 / Nn) - mu * mu;
    float scale = gamma[c] * rsqrtf((float)var + 1e-5f);
    float shift = beta[c] - (float)mu * scale;
    int idx = blockIdx.x * HID + c;
    float y = v[idx] * scale + shift;
    float r = act ? fmaxf(y, 0.f) : ((y > 0.f) ? y : expm1f(y));
    o[idx] = r;
    __nv_bfloat16 hi, lo;
    split1(r, hi, lo);
    g_hh[idx] = hi; g_hl[idx] = lo;
}

// ---------------- final projection ----------------
__global__ void proj3_k(const float* __restrict__ W, const float* __restrict__ b,
                        float* __restrict__ out) {
    int idx = blockIdx.x * 256 + threadIdx.x;
    if (idx >= Nn * 3) return;
    int n = idx / 3, o = idx % 3;
    float acc = b[o];
    const float* hrow = &g_h[n * HID];
    #pragma unroll 8
    for (int k = 0; k < HID; k++) acc += hrow[k] * W[k * 3 + o];
    out[idx] = acc;
}

// ---------------- launch ----------------
extern "C" void kernel_launch(void* const* d_in, const int* in_sizes, int n_in,
                              void* d_out, int out_size) {
    const float* x         = (const float*)d_in[0];
    const float* edge_attr = (const float*)d_in[1];
    const int*   ei        = (const int*)  d_in[2];
    const float* lift_W    = (const float*)d_in[3];
    const float* lift_b    = (const float*)d_in[4];
    const float* Wl        = (const float*)d_in[5];
    const float* bl        = (const float*)d_in[6];
    const float* Wr        = (const float*)d_in[7];
    const float* br        = (const float*)d_in[8];
    const float* We        = (const float*)d_in[9];
    const float* att       = (const float*)d_in[10];
    const float* conv_bias = (const float*)d_in[11];
    const float* bn_gamma  = (const float*)d_in[12];
    const float* bn_beta   = (const float*)d_in[13];
    const float* p1_W      = (const float*)d_in[14];
    const float* p1_b      = (const float*)d_in[15];
    const float* pbn1_g    = (const float*)d_in[16];
    const float* pbn1_b    = (const float*)d_in[17];
    const float* p2_W      = (const float*)d_in[18];
    const float* p2_b      = (const float*)d_in[19];
    const float* pbn2_g    = (const float*)d_in[20];
    const float* pbn2_b    = (const float*)d_in[21];
    const float* p3_W      = (const float*)d_in[22];
    const float* p3_b      = (const float*)d_in[23];
    float* out = (float*)d_out;

    float* d_h = nullptr; float* d_xl = nullptr; float* d_xr = nullptr; float* d_o = nullptr;
    __nv_bfloat16* d_Wbh = nullptr; __nv_bfloat16* d_Wbl = nullptr;
    cudaGetSymbolAddress((void**)&d_h,  g_h);
    cudaGetSymbolAddress((void**)&d_xl, g_xl);
    cudaGetSymbolAddress((void**)&d_xr, g_xr);
    cudaGetSymbolAddress((void**)&d_o,  g_out);
    cudaGetSymbolAddress((void**)&d_Wbh, g_Wbh);
    cudaGetSymbolAddress((void**)&d_Wbl, g_Wbl);

    cudaFuncSetAttribute(hgemm_k, cudaFuncAttributeMaxDynamicSharedMemorySize, GSM_DYN);

    const dim3 grid2((Nn + 127) / 128, 2, 2);
    const dim3 grid1((Nn + 127) / 128, 2, 1);
    const int WSL = HID * HID;

    wconv_k<<<12 * 256, 256>>>(Wl, Wr, p1_W, p2_W);
    zero_red_k<<<16, 256>>>();
    lift_k<<<Nn, HID>>>(x, lift_W, lift_b);
    // first gemm pair  <-- profiled slot
    hgemm_k<<<grid2, 256, GSM_DYN>>>(d_Wbh + 0 * WSL, d_Wbl + 0 * WSL, bl, d_xl,
                                     d_Wbh + 5 * WSL, d_Wbl + 5 * WSL, br, d_xr, Nn);
    ea_stats_k<<<64, 256>>>(edge_attr);
    ea_final_k<<<1, 32>>>();
    ea_norm_k<<<(Ee * EDGE_DIM + 255) / 256, 256>>>(edge_attr);
    zero_cnt_k<<<(Nn + 256) / 256, 256>>>();
    hist_k<<<Ee / 256, 256>>>(ei);
    scan_k<<<1, 1024>>>();
    fill_k<<<Ee / 256, 256>>>(ei);

    for (int t = 0; t < Tt; t++) {
        if (t > 0) {
            hgemm_k<<<grid2, 256, GSM_DYN>>>(d_Wbh + t * WSL, d_Wbl + t * WSL, bl + t * HID, d_xl,
                                             d_Wbh + (5 + t) * WSL, d_Wbl + (5 + t) * WSL, br + t * HID, d_xr, Nn);
        }
        attn_fused_k<<<Nn / GNODE, 128>>>(ei, We + t * EDGE_DIM * HID, att + t * HEADS * Cc,
                                          conv_bias + t * HID, t);
        bn_apply_k<<<Nn, HID>>>(d_o, d_h, 0, t, bn_gamma + t * HID, bn_beta + t * HID);
    }

    hgemm_k<<<grid1, 256, GSM_DYN>>>(d_Wbh + 10 * WSL, d_Wbl + 10 * WSL, p1_b, d_o,
                                     d_Wbh + 10 * WSL, d_Wbl + 10 * WSL, p1_b, d_o, Nn);
    bn_stats_k<<<80, 256>>>(d_o, 5);
    bn_apply_k<<<Nn, HID>>>(d_o, d_h, 1, 5, pbn1_g, pbn1_b);

    hgemm_k<<<grid1, 256, GSM_DYN>>>(d_Wbh + 11 * WSL, d_Wbl + 11 * WSL, p2_b, d_o,
                                     d_Wbh + 11 * WSL, d_Wbl + 11 * WSL, p2_b, d_o, Nn);
    bn_stats_k<<<80, 256>>>(d_o, 6);
    bn_apply_k<<<Nn, HID>>>(d_o, d_h, 1, 6, pbn2_g, pbn2_b);

    proj3_k<<<(Nn * 3 + 255) / 256, 256>>>(p3_W, p3_b, out);
}

// round 15
// speedup vs baseline: 1.1490x; 1.1490x over previous
#include <cuda_runtime.h>
#include <cuda_bf16.h>
#include <math.h>
#include <stdint.h>

#define Nn 10000
#define Ee 160000
#define HID 256
#define HEADS 8
#define Cc 32
#define Tt 5
#define EDGE_DIM 9
#define DCH 256   // edges per softmax chunk
#define GNODE 4   // nodes per attention block

// ---------------- scratch (static device globals; no allocation) ----------------
__device__ float g_ea[Ee * EDGE_DIM];
__device__ float g_h[Nn * HID];
__device__ float g_xl[Nn * HID];
__device__ float g_xr[Nn * HID];
__device__ float g_out[Nn * HID];
__device__ int   g_cnt[Nn + 1];
__device__ int   g_off[Nn + 1];
__device__ int   g_cur[Nn];
__device__ int   g_elist[Ee];
__device__ double g_red[8 * 512];   // slots: 0-4 GAT layers, 5-6 proj, 7 ea
__device__ float g_eap[2 * EDGE_DIM];
// bf16 hi/lo copies for tensor-core GEMM
__device__ __nv_bfloat16 g_hh[Nn * HID];
__device__ __nv_bfloat16 g_hl[Nn * HID];
__device__ __nv_bfloat16 g_Wbh[12 * HID * HID];
__device__ __nv_bfloat16 g_Wbl[12 * HID * HID];

// ---------------- utility ----------------
__global__ void zero_red_k() { int i = blockIdx.x * 256 + threadIdx.x; if (i < 8 * 512) g_red[i] = 0.0; }
__global__ void zero_cnt_k() { int i = blockIdx.x * 256 + threadIdx.x; if (i <= Nn) g_cnt[i] = 0; }

__device__ __forceinline__ void split1(float x, __nv_bfloat16& hi, __nv_bfloat16& lo) {
    hi = __float2bfloat16_rn(x);
    lo = __float2bfloat16_rn(x - __bfloat162float(hi));
}

// ---------------- weight pre-conversion: 12 slots of 256x256 ----------------
__global__ void wconv_k(const float* __restrict__ Wl, const float* __restrict__ Wr,
                        const float* __restrict__ p1, const float* __restrict__ p2) {
    int idx = blockIdx.x * 256 + threadIdx.x;
    int slot = idx >> 16, e = idx & 65535;
    float v;
    if (slot < 5)       v = Wl[slot * 65536 + e];
    else if (slot < 10) v = Wr[(slot - 5) * 65536 + e];
    else if (slot == 10) v = p1[e];
    else                 v = p2[e];
    __nv_bfloat16 hi, lo;
    split1(v, hi, lo);
    g_Wbh[idx] = hi; g_Wbl[idx] = lo;
}

// ---------------- edge-attr normalization (slot 7) ----------------
__global__ void ea_stats_k(const float* __restrict__ ea) {
    __shared__ double ss[EDGE_DIM], ss2[EDGE_DIM];
    if (threadIdx.x < EDGE_DIM) { ss[threadIdx.x] = 0.0; ss2[threadIdx.x] = 0.0; }
    __syncthreads();
    double ls[EDGE_DIM] = {0}, ls2[EDGE_DIM] = {0};
    for (int e = blockIdx.x * blockDim.x + threadIdx.x; e < Ee; e += gridDim.x * blockDim.x) {
        #pragma unroll
        for (int k = 0; k < EDGE_DIM; k++) {
            float x = ea[e * EDGE_DIM + k];
            ls[k] += x; ls2[k] += (double)x * x;
        }
    }
    #pragma unroll
    for (int k = 0; k < EDGE_DIM; k++) { atomicAdd(&ss[k], ls[k]); atomicAdd(&ss2[k], ls2[k]); }
    __syncthreads();
    if (threadIdx.x < EDGE_DIM) {
        atomicAdd(&g_red[7 * 512 + threadIdx.x], ss[threadIdx.x]);
        atomicAdd(&g_red[7 * 512 + 256 + threadIdx.x], ss2[threadIdx.x]);
    }
}

__global__ void ea_final_k() {
    int c = threadIdx.x;
    if (c < EDGE_DIM) {
        double mu = g_red[7 * 512 + c] / (double)Ee;
        double var = g_red[7 * 512 + 256 + c] / (double)Ee - mu * mu;
        double sd = sqrt(var > 0.0 ? var : 0.0);
        g_eap[c] = (float)mu;
        g_eap[EDGE_DIM + c] = (float)(1.0 / (sd + 1e-8));
    }
}

__global__ void ea_norm_k(const float* __restrict__ ea) {
    int idx = blockIdx.x * 256 + threadIdx.x;
    if (idx < Ee * EDGE_DIM) {
        int c = idx % EDGE_DIM;
        g_ea[idx] = (ea[idx] - g_eap[c]) * g_eap[EDGE_DIM + c];
    }
}

// ---------------- lift ----------------
__global__ void lift_k(const float* __restrict__ x, const float* __restrict__ W,
                       const float* __restrict__ b) {
    int n = blockIdx.x;
    int c = threadIdx.x;
    float acc = b[c];
    #pragma unroll
    for (int k = 0; k < 10; k++) acc += x[n * 10 + k] * W[k * HID + c];
    float h = fmaxf(acc, 0.f);
    g_h[n * HID + c] = h;
    __nv_bfloat16 hi, lo;
    split1(h, hi, lo);
    g_hh[n * HID + c] = hi; g_hl[n * HID + c] = lo;
}

// ---------------- CSR build ----------------
__global__ void hist_k(const int* __restrict__ ei) {
    int e = blockIdx.x * 256 + threadIdx.x;
    if (e < Ee) atomicAdd(&g_cnt[ei[Ee + e]], 1);
}

__global__ void scan_k() {
    __shared__ int partial[1024];
    int tid = threadIdx.x;
    const int PER = 10;
    int base = tid * PER;
    int loc[PER];
    int s = 0;
    #pragma unroll
    for (int i = 0; i < PER; i++) {
        int n = base + i;
        int v = (n < Nn) ? g_cnt[n] : 0;
        loc[i] = s; s += v;
    }
    partial[tid] = s;
    __syncthreads();
    for (int off = 1; off < 1024; off <<= 1) {
        int v = (tid >= off) ? partial[tid - off] : 0;
        __syncthreads();
        partial[tid] += v;
        __syncthreads();
    }
    int offset = (tid > 0) ? partial[tid - 1] : 0;
    #pragma unroll
    for (int i = 0; i < PER; i++) {
        int n = base + i;
        if (n < Nn) { g_off[n] = offset + loc[i]; g_cur[n] = offset + loc[i]; }
    }
    if (tid == 1023) g_off[Nn] = partial[1023];
}

__global__ void fill_k(const int* __restrict__ ei) {
    int e = blockIdx.x * 256 + threadIdx.x;
    if (e < Ee) {
        int pos = atomicAdd(&g_cur[ei[Ee + e]], 1);
        g_elist[pos] = e;
    }
}

// ================= bf16-split HMMA GEMM, cp.async double-buffered =================
// slot >= 0: accumulate per-channel BN sums of the (bias-added) output into g_red[slot].
#define STG_STRIDE 37888
#define GSM_DYN    (2 * STG_STRIDE)

__device__ __forceinline__ uint32_t smem_u32(const void* p) {
    uint32_t a;
    asm("{ .reg .u64 t; cvta.to.shared.u64 t, %1; cvt.u32.u64 %0, t; }" : "=r"(a) : "l"(p));
    return a;
}
__device__ __forceinline__ void cp16(uint32_t dst, const void* src) {
    asm volatile("cp.async.cg.shared.global [%0], [%1], 16;" :: "r"(dst), "l"(src) : "memory");
}
__device__ __forceinline__ void ldsm_x4(uint32_t* r, uint32_t addr) {
    asm volatile("ldmatrix.sync.aligned.m8n8.x4.shared.b16 {%0,%1,%2,%3}, [%4];"
                 : "=r"(r[0]), "=r"(r[1]), "=r"(r[2]), "=r"(r[3]) : "r"(addr));
}
__device__ __forceinline__ void ldsm_x4_t(uint32_t* r, uint32_t addr) {
    asm volatile("ldmatrix.sync.aligned.m8n8.x4.trans.shared.b16 {%0,%1,%2,%3}, [%4];"
                 : "=r"(r[0]), "=r"(r[1]), "=r"(r[2]), "=r"(r[3]) : "r"(addr));
}
__device__ __forceinline__ void mma_bf16(float& d0, float& d1, float& d2, float& d3,
                                         const uint32_t* a, uint32_t b0, uint32_t b1) {
    asm volatile(
        "mma.sync.aligned.m16n8k16.row.col.f32.bf16.bf16.f32 "
        "{%0,%1,%2,%3}, {%4,%5,%6,%7}, {%8,%9}, {%0,%1,%2,%3};"
        : "+f"(d0), "+f"(d1), "+f"(d2), "+f"(d3)
        : "r"(a[0]), "r"(a[1]), "r"(a[2]), "r"(a[3]), "r"(b0), "r"(b1));
}

__global__ void __launch_bounds__(256, 2)
hgemm_k(const __nv_bfloat16* __restrict__ Bh0, const __nv_bfloat16* __restrict__ Bl0,
        const float* __restrict__ b0, float* __restrict__ Y0,
        const __nv_bfloat16* __restrict__ Bh1, const __nv_bfloat16* __restrict__ Bl1,
        const float* __restrict__ b1, float* __restrict__ Y1,
        int M, int slot) {
    extern __shared__ __align__(16) char sm[];
    const uint32_t sb = smem_u32(sm);
    const int tid = threadIdx.x;
    const int wid = tid >> 5, lane = tid & 31;
    const int bm = blockIdx.x * 128, bn = blockIdx.y * 128;
    const __nv_bfloat16* Bh  = blockIdx.z ? Bh1 : Bh0;
    const __nv_bfloat16* Bl  = blockIdx.z ? Bl1 : Bl0;
    const float* bias        = blockIdx.z ? b1 : b0;
    float*       Y           = blockIdx.z ? Y1 : Y0;

    const int warp_m = (wid >> 1) * 32;
    const int warp_n = (wid & 1) * 64;

    const int ar = tid >> 1, akseg = (tid & 1) * 16;
    const int arow_g = min(bm + ar, M - 1);
    const __nv_bfloat16* gAh = g_hh + (size_t)arow_g * 256 + akseg;
    const __nv_bfloat16* gAl = g_hl + (size_t)arow_g * 256 + akseg;
    const int br_ = tid >> 3, bcseg = (tid & 7) * 16;
    const __nv_bfloat16* gBh = Bh + (size_t)br_ * 256 + bn + bcseg;
    const __nv_bfloat16* gBl = Bl + (size_t)br_ * 256 + bn + bcseg;
    const uint32_t aoff = (uint32_t)(ar * 80 + akseg * 2);
    const uint32_t boff = (uint32_t)(br_ * 272 + bcseg * 2);

    float acc[2][8][4];
    #pragma unroll
    for (int i = 0; i < 2; i++)
        #pragma unroll
        for (int j = 0; j < 8; j++)
            #pragma unroll
            for (int k = 0; k < 4; k++) acc[i][j][k] = 0.f;

    const uint32_t aRelH = (uint32_t)((warp_m + (lane & 15)) * 80 + (lane >> 4) * 16);
    const int bg = lane >> 3;
    const uint32_t bRelH = 20480u + (uint32_t)(((bg & 1) * 8 + (lane & 7)) * 272
                         + (warp_n + (bg >> 1) * 8) * 2);

    auto fill = [&](int c, int s) {
        uint32_t base = sb + (uint32_t)s * STG_STRIDE;
        const __nv_bfloat16* pa = gAh + c * 32;
        const __nv_bfloat16* pl = gAl + c * 32;
        const __nv_bfloat16* ph = gBh + (size_t)(c * 32) * 256;
        const __nv_bfloat16* pb = gBl + (size_t)(c * 32) * 256;
        cp16(base + aoff, pa);                 cp16(base + aoff + 16, pa + 8);
        cp16(base + 10240 + aoff, pl);         cp16(base + 10240 + aoff + 16, pl + 8);
        cp16(base + 20480 + boff, ph);         cp16(base + 20480 + boff + 16, ph + 8);
        cp16(base + 29184 + boff, pb);         cp16(base + 29184 + boff + 16, pb + 8);
        asm volatile("cp.async.commit_group;" ::: "memory");
    };

    fill(0, 0);

    #pragma unroll 1
    for (int kc = 0; kc < 8; kc++) {
        const int s = kc & 1;
        if (kc < 7) {
            fill(kc + 1, s ^ 1);
            asm volatile("cp.async.wait_group 1;" ::: "memory");
        } else {
            asm volatile("cp.async.wait_group 0;" ::: "memory");
        }
        __syncthreads();

        const uint32_t stg = sb + (uint32_t)s * STG_STRIDE;
        #pragma unroll
        for (int ks = 0; ks < 2; ks++) {
            uint32_t bh[4][4], bl[4][4];
            #pragma unroll
            for (int nt = 0; nt < 4; nt++) {
                uint32_t off = (uint32_t)(ks * 16) * 272 + (uint32_t)(nt * 16) * 2;
                ldsm_x4_t(bh[nt], stg + bRelH + off);
                ldsm_x4_t(bl[nt], stg + bRelH + 8704 + off);
            }
            #pragma unroll
            for (int mt = 0; mt < 2; mt++) {
                uint32_t ah[4], al[4];
                uint32_t aoff2 = (uint32_t)(mt * 16) * 80 + (uint32_t)(ks * 32);
                ldsm_x4(ah, stg + aRelH + aoff2);
                ldsm_x4(al, stg + 10240 + aRelH + aoff2);
                #pragma unroll
                for (int nt = 0; nt < 4; nt++) {
                    float* d0 = acc[mt][nt * 2];
                    float* d1 = acc[mt][nt * 2 + 1];
                    mma_bf16(d0[0], d0[1], d0[2], d0[3], ah, bh[nt][0], bh[nt][1]);
                    mma_bf16(d1[0], d1[1], d1[2], d1[3], ah, bh[nt][2], bh[nt][3]);
                    mma_bf16(d0[0], d0[1], d0[2], d0[3], ah, bl[nt][0], bl[nt][1]);
                    mma_bf16(d1[0], d1[1], d1[2], d1[3], ah, bl[nt][2], bl[nt][3]);
                    mma_bf16(d0[0], d0[1], d0[2], d0[3], al, bh[nt][0], bh[nt][1]);
                    mma_bf16(d1[0], d1[1], d1[2], d1[3], al, bh[nt][2], bh[nt][3]);
                }
            }
        }
        __syncthreads();
    }

    const int crow = lane >> 2, ccol = (lane & 3) * 2;
    float csum[16], csq[16];   // per-thread column partials (idx = nt8*2 + parity)
    #pragma unroll
    for (int i = 0; i < 16; i++) { csum[i] = 0.f; csq[i] = 0.f; }

    #pragma unroll
    for (int mt = 0; mt < 2; mt++) {
        int row0 = bm + warp_m + mt * 16 + crow;
        #pragma unroll
        for (int nt8 = 0; nt8 < 8; nt8++) {
            int col = bn + warp_n + nt8 * 8 + ccol;
            float bx = bias[col], by = bias[col + 1];
            if (row0 < M) {
                float ox = acc[mt][nt8][0] + bx, oy = acc[mt][nt8][1] + by;
                *reinterpret_cast<float2*>(Y + (size_t)row0 * 256 + col) = make_float2(ox, oy);
                csum[nt8 * 2] += ox;     csq[nt8 * 2] += ox * ox;
                csum[nt8 * 2 + 1] += oy; csq[nt8 * 2 + 1] += oy * oy;
            }
            if (row0 + 8 < M) {
                float ox = acc[mt][nt8][2] + bx, oy = acc[mt][nt8][3] + by;
                *reinterpret_cast<float2*>(Y + (size_t)(row0 + 8) * 256 + col) = make_float2(ox, oy);
                csum[nt8 * 2] += ox;     csq[nt8 * 2] += ox * ox;
                csum[nt8 * 2 + 1] += oy; csq[nt8 * 2 + 1] += oy * oy;
            }
        }
    }

    if (slot >= 0) {
        // lanes with equal (lane&3) share the same columns: reduce across them
        #pragma unroll
        for (int i = 0; i < 16; i++) {
            #pragma unroll
            for (int off = 4; off < 32; off <<= 1) {
                csum[i] += __shfl_xor_sync(0xffffffffu, csum[i], off);
                csq[i]  += __shfl_xor_sync(0xffffffffu, csq[i], off);
            }
        }
        if (lane < 4) {
            #pragma unroll
            for (int nt8 = 0; nt8 < 8; nt8++) {
                #pragma unroll
                for (int p = 0; p < 2; p++) {
                    int col = bn + warp_n + nt8 * 8 + lane * 2 + p;
                    atomicAdd(&g_red[slot * 512 + col], (double)csum[nt8 * 2 + p]);
                    atomicAdd(&g_red[slot * 512 + 256 + col], (double)csq[nt8 * 2 + p]);
                }
            }
        }
    }
}

// ================= fused GATv2 attention + BN stats (two-phase, R13) =================
__global__ void __launch_bounds__(128)
attn_fused_k(const int* __restrict__ ei, const float* __restrict__ We_,
             const float* __restrict__ att, const float* __restrict__ bias, int slot) {
    __shared__ float s_xr[256];
    __shared__ float s_lw[8][260];
    __shared__ int   s_src[DCH];

    const int tid = threadIdx.x, wid = tid >> 5, lane = tid & 31;

    float rWe[9][8], rAtt[8];
    {
        const float4* w4 = reinterpret_cast<const float4*>(We_);
        #pragma unroll
        for (int k = 0; k < 9; k++) {
            float4 a = w4[k * 64 + lane * 2];
            float4 b = w4[k * 64 + lane * 2 + 1];
            rWe[k][0] = a.x; rWe[k][1] = a.y; rWe[k][2] = a.z; rWe[k][3] = a.w;
            rWe[k][4] = b.x; rWe[k][5] = b.y; rWe[k][6] = b.z; rWe[k][7] = b.w;
        }
        const float4* a4 = reinterpret_cast<const float4*>(att);
        float4 a = a4[lane * 2], b = a4[lane * 2 + 1];
        rAtt[0] = a.x; rAtt[1] = a.y; rAtt[2] = a.z; rAtt[3] = a.w;
        rAtt[4] = b.x; rAtt[5] = b.y; rAtt[6] = b.z; rAtt[7] = b.w;
    }

    double bsum[2] = {0.0, 0.0}, bsq[2] = {0.0, 0.0};
    const float bj0 = bias[wid * 32 + lane];
    const float bj1 = bias[(wid + 4) * 32 + lane];

    #pragma unroll 1
    for (int g = 0; g < GNODE; g++) {
        const int n = blockIdx.x * GNODE + g;
        const int start = g_off[n], deg = g_off[n + 1] - start;

        __syncthreads();
        s_xr[tid] = g_xr[n * 256 + tid];
        s_xr[tid + 128] = g_xr[n * 256 + tid + 128];
        __syncthreads();

        float m[2] = {-INFINITY, -INFINITY};
        float den[2] = {0.f, 0.f};
        float acc[2] = {0.f, 0.f};

        for (int c0 = 0; c0 < deg; c0 += DCH) {
            const int cnt = min(DCH, deg - c0);

            for (int i0 = wid; i0 < cnt; i0 += 4) {
                int e = g_elist[start + c0 + i0];
                int src = __ldg(ei + e);
                if (lane == 0) s_src[i0] = src;
                float a9 = (lane < EDGE_DIM) ? g_ea[e * EDGE_DIM + lane] : 0.f;
                const float4* xl4 = reinterpret_cast<const float4*>(g_xl + (size_t)src * 256);
                float4 x0 = xl4[lane * 2], x1 = xl4[lane * 2 + 1];
                const float4* r4 = reinterpret_cast<const float4*>(s_xr);
                float4 r0 = r4[lane * 2], r1 = r4[lane * 2 + 1];
                float v[8];
                v[0] = x0.x + r0.x; v[1] = x0.y + r0.y; v[2] = x0.z + r0.z; v[3] = x0.w + r0.w;
                v[4] = x1.x + r1.x; v[5] = x1.y + r1.y; v[6] = x1.z + r1.z; v[7] = x1.w + r1.w;
                #pragma unroll
                for (int k = 0; k < EDGE_DIM; k++) {
                    float eak = __shfl_sync(0xffffffffu, a9, k);
                    #pragma unroll
                    for (int c = 0; c < 8; c++) v[c] = fmaf(eak, rWe[k][c], v[c]);
                }
                float p = 0.f;
                #pragma unroll
                for (int c = 0; c < 8; c++) {
                    float t = v[c] > 0.f ? v[c] : 0.2f * v[c];
                    p = fmaf(t, rAtt[c], p);
                }
                p += __shfl_xor_sync(0xffffffffu, p, 1);
                p += __shfl_xor_sync(0xffffffffu, p, 2);
                if ((lane & 3) == 0) s_lw[lane >> 2][i0] = p;
            }
            __syncthreads();

            #pragma unroll
            for (int j = 0; j < 2; j++) {
                const int h = wid + 4 * j;
                float cm = -INFINITY;
                for (int i = lane; i < cnt; i += 32) cm = fmaxf(cm, s_lw[h][i]);
                #pragma unroll
                for (int o = 16; o; o >>= 1) cm = fmaxf(cm, __shfl_xor_sync(0xffffffffu, cm, o));
                float mn = fmaxf(m[j], cm);
                float sc = expf(m[j] - mn);
                acc[j] *= sc; den[j] *= sc; m[j] = mn;
                float dp = 0.f;
                for (int i = lane; i < cnt; i += 32) {
                    float w = expf(s_lw[h][i] - mn);
                    s_lw[h][i] = w;
                    dp += w;
                }
                #pragma unroll
                for (int o = 16; o; o >>= 1) dp += __shfl_xor_sync(0xffffffffu, dp, o);
                den[j] += dp;
                const float* xlh = g_xl + h * 32 + lane;
                int i = 0;
                for (; i + 4 <= cnt; i += 4) {
                    float w0 = s_lw[h][i],     w1 = s_lw[h][i + 1];
                    float w2 = s_lw[h][i + 2], w3 = s_lw[h][i + 3];
                    int s0 = s_src[i], s1 = s_src[i + 1], s2 = s_src[i + 2], s3 = s_src[i + 3];
                    acc[j] += w0 * xlh[(size_t)s0 * 256] + w1 * xlh[(size_t)s1 * 256]
                            + w2 * xlh[(size_t)s2 * 256] + w3 * xlh[(size_t)s3 * 256];
                }
                for (; i < cnt; i++) acc[j] += s_lw[h][i] * xlh[(size_t)s_src[i] * 256];
            }
            __syncthreads();
        }

        #pragma unroll
        for (int j = 0; j < 2; j++) {
            const int h = wid + 4 * j, oc = h * 32 + lane;
            float b = j ? bj1 : bj0;
            float o = (deg == 0) ? b : acc[j] / (den[j] + 1e-16f) + b;
            g_out[n * 256 + oc] = o;
            bsum[j] += o; bsq[j] += (double)o * o;
        }
    }

    const int c0 = wid * 32 + lane;
    atomicAdd(&g_red[slot * 512 + c0],        bsum[0]);
    atomicAdd(&g_red[slot * 512 + 256 + c0],  bsq[0]);
    atomicAdd(&g_red[slot * 512 + c0 + 128],       bsum[1]);
    atomicAdd(&g_red[slot * 512 + 256 + c0 + 128], bsq[1]);
}

// ---------------- BatchNorm apply (slot-based) ----------------
// act: 0 = elu, 1 = relu; computes scale/shift from slot; emits bf16 hi/lo
__global__ void bn_apply_k(const float* __restrict__ v, float* __restrict__ o, int act,
                           int slot, const float* __restrict__ gamma,
                           const float* __restrict__ beta) {
    int c = threadIdx.x;
    double mu = g_red[slot * 512 + c] * (1.0 / Nn);
    double var = g_red[slot * 512 + 256 + c] * (1.0 / Nn) - mu * mu;
    float scale = gamma[c] * rsqrtf((float)var + 1e-5f);
    float shift = beta[c] - (float)mu * scale;
    int idx = blockIdx.x * HID + c;
    float y = v[idx] * scale + shift;
    float r = act ? fmaxf(y, 0.f) : ((y > 0.f) ? y : expm1f(y));
    o[idx] = r;
    __nv_bfloat16 hi, lo;
    split1(r, hi, lo);
    g_hh[idx] = hi; g_hl[idx] = lo;
}

// ---------------- final projection ----------------
__global__ void proj3_k(const float* __restrict__ W, const float* __restrict__ b,
                        float* __restrict__ out) {
    int idx = blockIdx.x * 256 + threadIdx.x;
    if (idx >= Nn * 3) return;
    int n = idx / 3, o = idx % 3;
    float acc = b[o];
    const float* hrow = &g_h[n * HID];
    #pragma unroll 8
    for (int k = 0; k < HID; k++) acc += hrow[k] * W[k * 3 + o];
    out[idx] = acc;
}

// ---------------- launch ----------------
extern "C" void kernel_launch(void* const* d_in, const int* in_sizes, int n_in,
                              void* d_out, int out_size) {
    const float* x         = (const float*)d_in[0];
    const float* edge_attr = (const float*)d_in[1];
    const int*   ei        = (const int*)  d_in[2];
    const float* lift_W    = (const float*)d_in[3];
    const float* lift_b    = (const float*)d_in[4];
    const float* Wl        = (const float*)d_in[5];
    const float* bl        = (const float*)d_in[6];
    const float* Wr        = (const float*)d_in[7];
    const float* br        = (const float*)d_in[8];
    const float* We        = (const float*)d_in[9];
    const float* att       = (const float*)d_in[10];
    const float* conv_bias = (const float*)d_in[11];
    const float* bn_gamma  = (const float*)d_in[12];
    const float* bn_beta   = (const float*)d_in[13];
    const float* p1_W      = (const float*)d_in[14];
    const float* p1_b      = (const float*)d_in[15];
    const float* pbn1_g    = (const float*)d_in[16];
    const float* pbn1_b    = (const float*)d_in[17];
    const float* p2_W      = (const float*)d_in[18];
    const float* p2_b      = (const float*)d_in[19];
    const float* pbn2_g    = (const float*)d_in[20];
    const float* pbn2_b    = (const float*)d_in[21];
    const float* p3_W      = (const float*)d_in[22];
    const float* p3_b      = (const float*)d_in[23];
    float* out = (float*)d_out;

    float* d_h = nullptr; float* d_xl = nullptr; float* d_xr = nullptr; float* d_o = nullptr;
    __nv_bfloat16* d_Wbh = nullptr; __nv_bfloat16* d_Wbl = nullptr;
    cudaGetSymbolAddress((void**)&d_h,  g_h);
    cudaGetSymbolAddress((void**)&d_xl, g_xl);
    cudaGetSymbolAddress((void**)&d_xr, g_xr);
    cudaGetSymbolAddress((void**)&d_o,  g_out);
    cudaGetSymbolAddress((void**)&d_Wbh, g_Wbh);
    cudaGetSymbolAddress((void**)&d_Wbl, g_Wbl);

    cudaFuncSetAttribute(hgemm_k, cudaFuncAttributeMaxDynamicSharedMemorySize, GSM_DYN);

    const dim3 grid2((Nn + 127) / 128, 2, 2);
    const dim3 grid1((Nn + 127) / 128, 2, 1);
    const int WSL = HID * HID;

    wconv_k<<<12 * 256, 256>>>(Wl, Wr, p1_W, p2_W);
    zero_red_k<<<16, 256>>>();
    lift_k<<<Nn, HID>>>(x, lift_W, lift_b);
    // first gemm pair  <-- profiled slot
    hgemm_k<<<grid2, 256, GSM_DYN>>>(d_Wbh + 0 * WSL, d_Wbl + 0 * WSL, bl, d_xl,
                                     d_Wbh + 5 * WSL, d_Wbl + 5 * WSL, br, d_xr, Nn, -1);
    ea_stats_k<<<64, 256>>>(edge_attr);
    ea_final_k<<<1, 32>>>();
    ea_norm_k<<<(Ee * EDGE_DIM + 255) / 256, 256>>>(edge_attr);
    zero_cnt_k<<<(Nn + 256) / 256, 256>>>();
    hist_k<<<Ee / 256, 256>>>(ei);
    scan_k<<<1, 1024>>>();
    fill_k<<<Ee / 256, 256>>>(ei);

    for (int t = 0; t < Tt; t++) {
        if (t > 0) {
            hgemm_k<<<grid2, 256, GSM_DYN>>>(d_Wbh + t * WSL, d_Wbl + t * WSL, bl + t * HID, d_xl,
                                             d_Wbh + (5 + t) * WSL, d_Wbl + (5 + t) * WSL, br + t * HID, d_xr, Nn, -1);
        }
        attn_fused_k<<<Nn / GNODE, 128>>>(ei, We + t * EDGE_DIM * HID, att + t * HEADS * Cc,
                                          conv_bias + t * HID, t);
        bn_apply_k<<<Nn, HID>>>(d_o, d_h, 0, t, bn_gamma + t * HID, bn_beta + t * HID);
    }

    // projection MLP: BN stats fused into gemm epilogue (slots 5, 6)
    hgemm_k<<<grid1, 256, GSM_DYN>>>(d_Wbh + 10 * WSL, d_Wbl + 10 * WSL, p1_b, d_o,
                                     d_Wbh + 10 * WSL, d_Wbl + 10 * WSL, p1_b, d_o, Nn, 5);
    bn_apply_k<<<Nn, HID>>>(d_o, d_h, 1, 5, pbn1_g, pbn1_b);

    hgemm_k<<<grid1, 256, GSM_DYN>>>(d_Wbh + 11 * WSL, d_Wbl + 11 * WSL, p2_b, d_o,
                                     d_Wbh + 11 * WSL, d_Wbl + 11 * WSL, p2_b, d_o, Nn, 6);
    bn_apply_k<<<Nn, HID>>>(d_o, d_h, 1, 6, pbn2_g, pbn2_b);

    proj3_k<<<(Nn * 3 + 255) / 256, 256>>>(p3_W, p3_b, out);
}